// round 15
// baseline (speedup 1.0000x reference)
#include <cuda_runtime.h>
#include <cuda_fp16.h>
#include <math.h>

typedef unsigned long long ull;
typedef unsigned int u32;

// ---------------- device scratch (allocations are forbidden) ----------------
__device__ float g_Pvis[1024*512];   // people  @ Wvis[0:1024]
__device__ float g_Ovis[1024*512];   // objects @ Wvis[1024:2048]
__device__ float g_Cvis[64*512];     // context @ Wvis[2048:3072] + Wvis_b
__device__ float g_HO[1024*1024];    // relu(people  @ Who + b)
__device__ float g_OH[1024*1024];    // relu(objects @ Woh + b)
__device__ float g_adj[16384];       // sigmoid(i_ho)
__device__ float g_PR[1024*1024];    // people_r
__device__ float g_OBF[1024*1024];   // objects_full
__device__ float g_Gp[1024*29];
__device__ float g_Go[1024*29];

// packed head weights, fp16 hi only, [c=64][k=512]
__device__ __half g_Wcath[64*512];

// fp16 pre-converted operands (A side hi/lo, B side hi only)
__device__ __half g_peh[1024*1024], g_pel[1024*1024];
__device__ __half g_obh[1024*1024], g_obl[1024*1024];
__device__ __half g_cxh[128*1024],  g_cxl[128*1024];
__device__ __half g_Bv0h[512*1024];
__device__ __half g_Bv1h[512*1024];
__device__ __half g_Bv2h[512*1024];
__device__ __half g_Whoh[1024*1024];
__device__ __half g_Wohh[1024*1024];
__device__ __half g_sph[16384*32], g_spl[16384*32];   // spatial h/l
__device__ __half g_Wsh[512*32];                      // Wspat^T [n][k] hi

// ---------------- small helpers ----------------
__device__ __forceinline__ u32 smem_u32(const void* p){
    u32 a; asm("{ .reg .u64 t; cvta.to.shared.u64 t, %1; cvt.u32.u64 %0, t; }":"=r"(a):"l"(p)); return a;
}
__device__ __forceinline__ void ldm_x4(u32* r, u32 addr){
    asm volatile("ldmatrix.sync.aligned.m8n8.x4.shared.b16 {%0,%1,%2,%3}, [%4];"
        :"=r"(r[0]),"=r"(r[1]),"=r"(r[2]),"=r"(r[3]):"r"(addr));
}
__device__ __forceinline__ void mma_f16(float* c, const u32* a, const u32* b){
    asm volatile("mma.sync.aligned.m16n8k16.row.col.f32.f16.f16.f32 "
        "{%0,%1,%2,%3}, {%4,%5,%6,%7}, {%8,%9}, {%0,%1,%2,%3};"
        :"+f"(c[0]),"+f"(c[1]),"+f"(c[2]),"+f"(c[3])
        :"r"(a[0]),"r"(a[1]),"r"(a[2]),"r"(a[3]),"r"(b[0]),"r"(b[1]));
}
__device__ __forceinline__ void cp16(u32 dst, const void* src){
    asm volatile("cp.async.cg.shared.global [%0], [%1], 16;"::"r"(dst),"l"(src));
}
// pack (x,y) -> fp16x2 word (hi only)
__device__ __forceinline__ u32 pack2(float x, float y){
    __half2 h = __floats2half2_rn(x, y);
    return *(u32*)&h;
}

// ---------------- c_prep1: convA + convB + head-pack (k1 + k2-heads deps) ----------------
__global__ __launch_bounds__(256) void c_prep1(
    const float* __restrict__ people, const float* __restrict__ objects,
    const float* __restrict__ context,
    const float* __restrict__ Wvis_w, const float* __restrict__ Who_w,
    const float* __restrict__ Woh_w,
    const float* __restrict__ Wip_w,  const float* __restrict__ Wref_w,
    const float* __restrict__ Watt_w)
{
    __shared__ float t[32][33];
    int bid = blockIdx.x;
    int tid = threadIdx.x;

    if (bid < 8704) {                                 // ---- convA (hi/lo) ----
        int idx = bid*256 + tid;
        const float* src; __half *dh, *dl; int e;
        if (idx < 1048576)      { src = people;  dh = g_peh; dl = g_pel; e = idx; }
        else if (idx < 2097152) { src = objects; dh = g_obh; dl = g_obl; e = idx - 1048576; }
        else                    { src = context; dh = g_cxh; dl = g_cxl; e = idx - 2097152; }
        float v = 0.f;
        if (dh != g_cxh || (e >> 10) < 64) v = src[e];
        __half h = __float2half(v);
        dh[e] = h;
        dl[e] = __float2half(v - __half2float(h));
    } else if (bid < 12288) {                         // ---- convB (transpose, hi only) ----
        int lb = bid - 8704;
        const float* W; __half *dh; int N, local;
        if (lb < 512)        { W = Wvis_w;            dh = g_Bv0h; N = 512;  local = lb;       }
        else if (lb < 1024)  { W = Wvis_w + 1024*512; dh = g_Bv1h; N = 512;  local = lb - 512; }
        else if (lb < 1536)  { W = Wvis_w + 2048*512; dh = g_Bv2h; N = 512;  local = lb - 1024;}
        else if (lb < 2560)  { W = Who_w;             dh = g_Whoh; N = 1024; local = lb - 1536;}
        else                 { W = Woh_w;             dh = g_Wohh; N = 1024; local = lb - 2560;}
        int ntN = N >> 5;
        int k0 = (local / ntN) * 32, n0 = (local % ntN) * 32;
        #pragma unroll
        for (int i = 0; i < 4; i++) {
            int e = tid + i*256, r = e >> 5, c = e & 31;
            t[r][c] = W[(k0 + r)*N + n0 + c];
        }
        __syncthreads();
        #pragma unroll
        for (int i = 0; i < 4; i++) {
            int e = tid + i*256, r = e >> 5, c = e & 31;
            dh[(n0 + r)*1024 + k0 + c] = __float2half(t[c][r]);
        }
    } else {                                          // ---- head-weight pack (hi only) ----
        int idx = (bid - 12288)*256 + tid;
        int c = idx >> 9, k = idx & 511;
        float v = 0.f;
        if (c == 0)                  v = Wip_w[k];
        else if (c <= 29)            v = Wref_w[k*29 + c - 1];
        else if (c >= 32 && c <= 60) v = Watt_w[k*29 + c - 32];
        g_Wcath[idx] = __float2half(v);
    }
}

// ---------------- c_prep2: spatial + Wspat^T (k2-phase1 deps, independent) ----------------
__global__ __launch_bounds__(256) void c_prep2(
    const float* __restrict__ spatial, const float* __restrict__ Wspat_w)
{
    int bid = blockIdx.x;
    int tid = threadIdx.x;
    if (bid < 2048) {                                 // ---- spatial conv (hi/lo) ----
        int idx = bid*256 + tid;                      // 524288
        float v = spatial[idx];
        __half h = __float2half(v);
        g_sph[idx] = h;
        g_spl[idx] = __float2half(v - __half2float(h));
    } else {                                          // ---- Wspat^T (hi only) ----
        int idx = (bid - 2048)*256 + tid;             // 16384
        g_Wsh[idx] = __float2half(Wspat_w[(idx & 31)*512 + (idx >> 5)]);
    }
}

// ---------------- k1: warp-MMA fp16 2-term split GEMM, 128x64 tiles ----------------
#define KP 40
#define TA (128*KP*2)
#define TB (64*KP*2)
#define STAGE_B (2*TA + TB)          // Ah, Al, Bh = 25600
#define K1_SMEM (2*STAGE_B)          // 51200

__global__ __launch_bounds__(128,3) void k1_mma(
    const float* __restrict__ Wvis_b,
    const float* __restrict__ Who_b,
    const float* __restrict__ Woh_b)
{
    extern __shared__ char smem[];
    u32 sb = smem_u32(smem);
    int tid = threadIdx.x, lane = tid & 31, wid = tid >> 5;
    int wm = wid & 1, wn = wid >> 1;
    int bid = blockIdx.x;

    const __half *Ah, *Al, *Bh;
    float* C; const float* bias = 0;
    int relu = 0, Mv = 1024, N, mt0, nt0, local;
    if (bid < 64)       { Ah=g_peh; Al=g_pel; Bh=g_Bv0h; C=g_Pvis; N=512;  local=bid;     mt0=local>>3; nt0=local&7; }
    else if (bid < 128) { Ah=g_obh; Al=g_obl; Bh=g_Bv1h; C=g_Ovis; N=512;  local=bid-64;  mt0=local>>3; nt0=local&7; }
    else if (bid < 136) { Ah=g_cxh; Al=g_cxl; Bh=g_Bv2h; C=g_Cvis; N=512;  local=bid-128; mt0=0; nt0=local; bias=Wvis_b; Mv=64; }
    else if (bid < 264) { Ah=g_peh; Al=g_pel; Bh=g_Whoh; C=g_HO;   N=1024; local=bid-136; mt0=local>>4; nt0=local&15; bias=Who_b; relu=1; }
    else                { Ah=g_obh; Al=g_obl; Bh=g_Wohh; C=g_OH;   N=1024; local=bid-264; mt0=local>>4; nt0=local&15; bias=Woh_b; relu=1; }
    int m0 = mt0 * 128, n0 = nt0 * 64;

    float acc[4][4][4];
    #pragma unroll
    for (int i = 0; i < 4; i++)
        #pragma unroll
        for (int j = 0; j < 4; j++)
            #pragma unroll
            for (int q = 0; q < 4; q++) acc[i][j][q] = 0.f;

    int lg = lane >> 3, lr = lane & 7;
    int a_row_off = lr + ((lg & 1) << 3);
    int a_k_off   = (lg >> 1) << 3;
    int b4_row_off = ((lane >> 4) << 3) + lr;
    int b4_k_off   = ((lane >> 3) & 1) << 3;

    #define LOAD_STAGE(KT, S) do {                                                    \
        u32 _s = (S); int _kt = (KT);                                                 \
        _Pragma("unroll")                                                             \
        for (int i = 0; i < 4; i++) {                                                 \
            int e = tid + i*128, row = e >> 2, sg = (e & 3) * 8;                      \
            cp16(_s      + (row*KP + sg)*2, &Ah[(m0 + row)*1024 + _kt + sg]);         \
            cp16(_s + TA + (row*KP + sg)*2, &Al[(m0 + row)*1024 + _kt + sg]);         \
        }                                                                             \
        _Pragma("unroll")                                                             \
        for (int i = 0; i < 2; i++) {                                                 \
            int e = tid + i*128, row = e >> 2, sg = (e & 3) * 8;                      \
            cp16(_s + 2*TA + (row*KP + sg)*2, &Bh[(n0 + row)*1024 + _kt + sg]);       \
        }                                                                             \
        asm volatile("cp.async.commit_group;");                                       \
    } while(0)

    LOAD_STAGE(0, sb);

    for (int c = 0; c < 32; c++) {
        asm volatile("cp.async.wait_group 0;");
        __syncthreads();
        if (c < 31) LOAD_STAGE((c + 1)*32, sb + ((c + 1) & 1)*STAGE_B);

        u32 st  = sb + (c & 1)*STAGE_B;
        u32 sAh = st, sAl = st + TA, sBh = st + 2*TA;

        #pragma unroll
        for (int ks = 0; ks < 32; ks += 16) {
            u32 bh[4][2];
            #pragma unroll
            for (int j = 0; j < 2; j++) {
                u32 boff2 = ((wn*32 + j*16 + b4_row_off)*KP + ks + b4_k_off) * 2;
                u32 r4[4];
                ldm_x4(r4, sBh + boff2);
                bh[j*2][0] = r4[0]; bh[j*2][1] = r4[1]; bh[j*2+1][0] = r4[2]; bh[j*2+1][1] = r4[3];
            }
            #pragma unroll
            for (int mt = 0; mt < 4; mt++) {
                u32 aoff = ((wm*64 + mt*16 + a_row_off)*KP + ks + a_k_off) * 2;
                u32 ah[4], al[4];
                ldm_x4(ah, sAh + aoff);
                ldm_x4(al, sAl + aoff);
                #pragma unroll
                for (int nt = 0; nt < 4; nt++) {
                    mma_f16(acc[mt][nt], ah, bh[nt]);
                    mma_f16(acc[mt][nt], al, bh[nt]);
                }
            }
        }
    }

    int rq = lane >> 2, cq = (lane & 3) * 2;
    #pragma unroll
    for (int mt = 0; mt < 4; mt++) {
        int gmA = m0 + wm*64 + mt*16 + rq;
        int gmB = gmA + 8;
        #pragma unroll
        for (int nt = 0; nt < 4; nt++) {
            int gn = n0 + wn*32 + nt*8 + cq;
            float b0 = bias ? bias[gn]   : 0.f;
            float b1 = bias ? bias[gn+1] : 0.f;
            float v0 = acc[mt][nt][0] + b0, v1 = acc[mt][nt][1] + b1;
            float v2 = acc[mt][nt][2] + b0, v3 = acc[mt][nt][3] + b1;
            if (relu) { v0=fmaxf(v0,0.f); v1=fmaxf(v1,0.f); v2=fmaxf(v2,0.f); v3=fmaxf(v3,0.f); }
            if (gmA < Mv) *(float2*)&C[gmA*N + gn] = make_float2(v0, v1);
            if (gmB < Mv) *(float2*)&C[gmB*N + gn] = make_float2(v2, v3);
        }
    }
}

// ---------------- k2: per-(b,p) MMA phase1 (a_ho/f_ref) + MMA heads ----------------
// smem layout (bytes):
//   [0      ) A hi tile   16x40 fp16 = 1280
//   [1280   ) A lo tile   = 1280
//   [2560   ) Wsh staged  512x40 fp16 = 40960
//   [43520  ) f/a hi      32x520 fp16 = 33280
#define K2P 520
#define OFF_AH  0
#define OFF_AL  1280
#define OFF_WS  2560
#define OFF_FAH 43520
#define K2_SMEM 76800

__global__ __launch_bounds__(256,2) void k2_pairs(
    const float* __restrict__ Wspat_b,
    const float* __restrict__ Wip_b,   const float* __restrict__ Wref_b,
    const float* __restrict__ Watt_b,  float* __restrict__ out)
{
    extern __shared__ char sm2[];
    __half* s_ws  = (__half*)(sm2 + OFF_WS);    // [512][40]
    __half* s_fah = (__half*)(sm2 + OFF_FAH);   // [32][520]

    int tid = threadIdx.x;
    int bp = blockIdx.x;
    int b = bp >> 4;
    int lane = tid & 31, wid = tid >> 5;

    // ---- phase 1: load spatial tile [16][32] fp16 h/l + Wsh [512][32] into smem ----
    {
        int l = tid >> 4, kq = tid & 15;
        ((u32*)(sm2 + OFF_AH))[l*20 + kq] = ((const u32*)g_sph)[(bp*16 + l)*16 + kq];
        ((u32*)(sm2 + OFF_AL))[l*20 + kq] = ((const u32*)g_spl)[(bp*16 + l)*16 + kq];
    }
    #pragma unroll
    for (int i = 0; i < 8; i++) {
        int e = tid + i*256;            // 0..2047
        int n = e >> 2, seg = (e & 3) * 8;
        *(uint4*)&s_ws[n*40 + seg] = *(const uint4*)&g_Wsh[n*32 + seg];
    }
    __syncthreads();

    int lg = lane >> 3, lr = lane & 7;
    int a_row_off = lr + ((lg & 1) << 3);
    int a_koff = (lg >> 1) << 3;
    u32 ah0[4], ah1[4], al0[4], al1[4];
    {
        u32 bah = smem_u32(sm2 + OFF_AH), bal = smem_u32(sm2 + OFF_AL);
        u32 aoff = (a_row_off*40 + a_koff)*2;
        ldm_x4(ah0, bah + aoff);
        ldm_x4(ah1, bah + aoff + 32);
        ldm_x4(al0, bal + aoff);
        ldm_x4(al1, bal + aoff + 32);
    }

    // phase1 MMA: warp w covers n-cols w*64..+63; B frags via ldmatrix from s_ws
    int lq = lane & 3, ln = lane >> 2;
    u32 base_ws = smem_u32(s_ws);
    int ws_koff = (lane >> 3) << 3;
    #pragma unroll
    for (int nt = 0; nt < 8; nt++) {
        u32 bh[4];
        ldm_x4(bh, base_ws + ((wid*64 + nt*8 + lr)*40 + ws_koff)*2);
        float c[4] = {0.f, 0.f, 0.f, 0.f};
        mma_f16(c, ah0, bh);
        mma_f16(c, al0, bh);
        mma_f16(c, ah1, bh + 2);
        mma_f16(c, al1, bh + 2);

        // fused epilogue -> s_fah (hi only)
        int j0 = wid*64 + nt*8 + lq*2;
        int l0 = ln, l1 = ln + 8;
        float2 bs = *(const float2*)&Wspat_b[j0];
        float2 pv = *(const float2*)&g_Pvis[bp*512 + j0];
        float2 cv = *(const float2*)&g_Cvis[b*512 + j0];
        float2 o0 = *(const float2*)&g_Ovis[(b*16 + l0)*512 + j0];
        float2 o1 = *(const float2*)&g_Ovis[(b*16 + l1)*512 + j0];
        float a0 = fmaxf(c[0] + bs.x, 0.f), a1 = fmaxf(c[1] + bs.y, 0.f);
        float a2 = fmaxf(c[2] + bs.x, 0.f), a3 = fmaxf(c[3] + bs.y, 0.f);
        float f0 = fmaxf(pv.x + o0.x + cv.x, 0.f) * a0;
        float f1 = fmaxf(pv.y + o0.y + cv.y, 0.f) * a1;
        float f2 = fmaxf(pv.x + o1.x + cv.x, 0.f) * a2;
        float f3 = fmaxf(pv.y + o1.y + cv.y, 0.f) * a3;
        *(u32*)&s_fah[l0*K2P + j0]        = pack2(f0, f1);
        *(u32*)&s_fah[l1*K2P + j0]        = pack2(f2, f3);
        *(u32*)&s_fah[(16 + l0)*K2P + j0] = pack2(a0, a1);
        *(u32*)&s_fah[(16 + l1)*K2P + j0] = pack2(a2, a3);
    }
    __syncthreads();

    // ---- phase 2: [32 rows] @ heads; B frags DIRECT from global (L2-hot 64KB) ----
    int mt = wid >> 2;
    int ntile = (wid & 3) + mt*4;
    u32 base_fah = smem_u32(s_fah);
    int a_row = mt*16 + lr + ((lg & 1) << 3);
    int n = ntile*8 + ln;                    // this lane's c-row of g_Wcath
    const u32* WcU = (const u32*)g_Wcath;    // [64 rows][256 words]

    float acc2[4] = {0.f, 0.f, 0.f, 0.f};

    #pragma unroll 4
    for (int ks = 0; ks < 512; ks += 32) {
        u32 xh0[4], xh1[4];
        ldm_x4(xh0, base_fah + (a_row*K2P + ks + a_koff)*2);
        ldm_x4(xh1, base_fah + (a_row*K2P + ks + 16 + a_koff)*2);
        u32 b0[2], b1[2];
        b0[0] = WcU[n*256 + (ks >> 1) + lq];
        b0[1] = WcU[n*256 + (ks >> 1) + 4 + lq];
        b1[0] = WcU[n*256 + (ks >> 1) + 8 + lq];
        b1[1] = WcU[n*256 + (ks >> 1) + 12 + lq];
        mma_f16(acc2, xh0, b0);
        mma_f16(acc2, xh1, b1);
    }

    // ---- outputs ----
    int r0 = mt*16 + (lane >> 2);
    int c0 = ntile*8 + (lane & 3)*2;
    #pragma unroll
    for (int q = 0; q < 4; q++) {
        int r = r0 + ((q >> 1) << 3);
        int c = c0 + (q & 1);
        float v = acc2[q];
        if (r < 16) {
            int cidx = bp*16 + r;
            if (c == 0) {
                v += Wip_b[0];
                out[cidx] = v;
                g_adj[cidx] = 1.f / (1.f + expf(-v));
            } else if (c <= 29) {
                out[16384 + cidx*29 + (c - 1)] = v + Wref_b[c - 1];
            }
        } else {
            int cidx = bp*16 + (r - 16);
            int cc = c - 32;
            if (cc >= 0 && cc <= 28) {
                out[491520 + cidx*29 + cc] = v + Watt_b[cc];
            }
        }
    }
}

// ---------------- k3a: message passing ----------------
__global__ __launch_bounds__(256) void k3a_msg(const float* __restrict__ people,
                                               const float* __restrict__ objects)
{
    __shared__ float adj[240];
    int bid = blockIdx.x;                 // 512
    int b = bid >> 3, ch = (bid >> 1) & 3, role = bid & 1;
    int tid = threadIdx.x;
    if (tid < 240) adj[tid] = g_adj[(b*16 + tid/15)*16 + (tid % 15) + 1];
    __syncthreads();

    int d = ch*256 + tid;
    if (role == 0) {
        float oh[15];
        #pragma unroll
        for (int o = 0; o < 15; o++) oh[o] = g_OH[(b*16 + o + 1)*1024 + d];
        #pragma unroll
        for (int p = 0; p < 16; p++) {
            float acc = people[(b*16 + p)*1024 + d];
            #pragma unroll
            for (int o = 0; o < 15; o++) acc += adj[p*15 + o] * oh[o];
            g_PR[(b*16 + p)*1024 + d] = acc;
        }
    } else {
        float ho[16];
        #pragma unroll
        for (int p = 0; p < 16; p++) ho[p] = g_HO[(b*16 + p)*1024 + d];
        g_OBF[(b*16)*1024 + d] = objects[(b*16)*1024 + d];
        #pragma unroll
        for (int o = 0; o < 15; o++) {
            float acc = objects[(b*16 + o + 1)*1024 + d];
            #pragma unroll
            for (int p = 0; p < 16; p++) acc += adj[p*15 + o] * ho[p];
            g_OBF[(b*16 + o + 1)*1024 + d] = acc;
        }
    }
}

// ---------------- k3b: skinny GEMM [2048,1024]@[1024,29] warp-per-row ----------------
__global__ __launch_bounds__(256) void k3b_gemm(const float* __restrict__ Wg_w,
                                                const float* __restrict__ Wg_b)
{
    __shared__ float Ws[256*33];
    int half = blockIdx.x >> 7;
    int row = (blockIdx.x & 127)*8 + (threadIdx.x >> 5);
    int lane = threadIdx.x & 31;
    const float* src = half ? g_OBF : g_PR;
    const float* W = Wg_w + half*1024*29;
    float* dst = half ? g_Go : g_Gp;

    float acc[29];
    #pragma unroll
    for (int a = 0; a < 29; a++) acc[a] = 0.f;

    for (int kt = 0; kt < 4; kt++) {
        __syncthreads();
        #pragma unroll
        for (int i = 0; i < 29; i++) {
            int idx = threadIdx.x + i*256;
            int k = idx / 29, a = idx - k*29;
            Ws[k*33 + a] = W[kt*7424 + idx];
        }
        __syncthreads();
        #pragma unroll
        for (int t = 0; t < 8; t++) {
            int k = t*32 + lane;
            float rv = src[row*1024 + kt*256 + k];
            #pragma unroll
            for (int a = 0; a < 29; a++) acc[a] += rv * Ws[k*33 + a];
        }
    }
    #pragma unroll
    for (int off = 16; off; off >>= 1)
        #pragma unroll
        for (int a = 0; a < 29; a++)
            acc[a] += __shfl_down_sync(0xffffffffu, acc[a], off);
    if (lane == 0) {
        #pragma unroll
        for (int a = 0; a < 29; a++)
            dst[row*29 + a] = acc[a] + (half ? Wg_b[a] : 0.f);
    }
}

// ---------------- k3c: broadcast add -> p_graph ----------------
__global__ __launch_bounds__(256) void k3c_add(float* __restrict__ out_pg)
{
    int idx = blockIdx.x*256 + threadIdx.x;
    int c = idx / 29;
    int a = idx - c*29;
    int prow = c >> 4;
    int lrow = (c >> 8)*16 + (c & 15);
    out_pg[idx] = g_Gp[prow*29 + a] + g_Go[lrow*29 + a];
}

// ---------------- launch: single k1; only c_prep2 forked ----------------
extern "C" void kernel_launch(void* const* d_in, const int* in_sizes, int n_in,
                              void* d_out, int out_size) {
    const float* people  = (const float*)d_in[0];
    const float* objects = (const float*)d_in[1];
    const float* context = (const float*)d_in[2];
    const float* spatial = (const float*)d_in[3];
    const float* Wvis_w  = (const float*)d_in[4];
    const float* Wvis_b  = (const float*)d_in[5];
    const float* Wspat_w = (const float*)d_in[6];
    const float* Wspat_b = (const float*)d_in[7];
    const float* Wip_w   = (const float*)d_in[8];
    const float* Wip_b   = (const float*)d_in[9];
    const float* Wref_w  = (const float*)d_in[10];
    const float* Wref_b  = (const float*)d_in[11];
    const float* Watt_w  = (const float*)d_in[12];
    const float* Watt_b  = (const float*)d_in[13];
    const float* Woh_w   = (const float*)d_in[14];
    const float* Woh_b   = (const float*)d_in[15];
    const float* Who_w   = (const float*)d_in[16];
    const float* Who_b   = (const float*)d_in[17];
    const float* Wg_w    = (const float*)d_in[18];
    const float* Wg_b    = (const float*)d_in[19];
    float* out = (float*)d_out;

    cudaFuncSetAttribute(k1_mma,  cudaFuncAttributeMaxDynamicSharedMemorySize, K1_SMEM);
    cudaFuncSetAttribute(k2_pairs, cudaFuncAttributeMaxDynamicSharedMemorySize, K2_SMEM);

    cudaStream_t s1;
    cudaStreamCreateWithFlags(&s1, cudaStreamNonBlocking);
    cudaEvent_t evF, ev2;
    cudaEventCreateWithFlags(&evF, cudaEventDisableTiming);
    cudaEventCreateWithFlags(&ev2, cudaEventDisableTiming);

    // fork point: side stream first waits on an origin-stream event
    cudaEventRecord(evF, 0);
    cudaStreamWaitEvent(s1, evF, 0);

    // side stream: k2-only conversions (overlap with c_prep1 + k1)
    c_prep2<<<2112, 256, 0, s1>>>(spatial, Wspat_w);
    cudaEventRecord(ev2, s1);

    // origin stream: main conversions, then full k1
    c_prep1<<<12416, 256>>>(people, objects, context,
                            Wvis_w, Who_w, Woh_w, Wip_w, Wref_w, Watt_w);
    k1_mma<<<392, 128, K1_SMEM>>>(Wvis_b, Who_b, Woh_b);

    // k2 needs c_prep2 output too
    cudaStreamWaitEvent(0, ev2, 0);
    k2_pairs<<<1024, 256, K2_SMEM>>>(Wspat_b, Wip_b, Wref_b, Watt_b, out);

    k3a_msg<<<512, 256>>>(people, objects);
    k3b_gemm<<<256, 256>>>(Wg_w, Wg_b);
    k3c_add<<<1856, 256>>>(out + 966656);

    cudaEventDestroy(evF);
    cudaEventDestroy(ev2);
    cudaStreamDestroy(s1);
}

// round 16
// speedup vs baseline: 1.1230x; 1.1230x over previous
#include <cuda_runtime.h>
#include <cuda_fp16.h>
#include <math.h>

typedef unsigned long long ull;
typedef unsigned int u32;

// ---------------- device scratch (allocations are forbidden) ----------------
__device__ float g_Pvis[1024*512];
__device__ float g_Ovis[1024*512];
__device__ float g_Cvis[64*512];
__device__ float g_HO[1024*1024];
__device__ float g_OH[1024*1024];
__device__ float g_adj[16384];
__device__ float g_PR[1024*1024];
__device__ float g_OBF[1024*1024];
__device__ float g_Gp[1024*29];
__device__ float g_Go[1024*29];

__device__ __half g_Wcath[64*512];           // packed head weights [c=64][k=512]

__device__ __half g_peh[1024*1024], g_pel[1024*1024];
__device__ __half g_obh[1024*1024], g_obl[1024*1024];
__device__ __half g_cxh[128*1024],  g_cxl[128*1024];
__device__ __half g_Bv0h[512*1024];
__device__ __half g_Bv1h[512*1024];
__device__ __half g_Bv2h[512*1024];
__device__ __half g_Whoh[1024*1024];
__device__ __half g_Wohh[1024*1024];
__device__ __half g_sph[16384*32], g_spl[16384*32];
__device__ __half g_Wsh[512*32];

// ---------------- small helpers ----------------
__device__ __forceinline__ u32 smem_u32(const void* p){
    u32 a; asm("{ .reg .u64 t; cvta.to.shared.u64 t, %1; cvt.u32.u64 %0, t; }":"=r"(a):"l"(p)); return a;
}
__device__ __forceinline__ void ldm_x4(u32* r, u32 addr){
    asm volatile("ldmatrix.sync.aligned.m8n8.x4.shared.b16 {%0,%1,%2,%3}, [%4];"
        :"=r"(r[0]),"=r"(r[1]),"=r"(r[2]),"=r"(r[3]):"r"(addr));
}
__device__ __forceinline__ void mma_f16(float* c, const u32* a, const u32* b){
    asm volatile("mma.sync.aligned.m16n8k16.row.col.f32.f16.f16.f32 "
        "{%0,%1,%2,%3}, {%4,%5,%6,%7}, {%8,%9}, {%0,%1,%2,%3};"
        :"+f"(c[0]),"+f"(c[1]),"+f"(c[2]),"+f"(c[3])
        :"r"(a[0]),"r"(a[1]),"r"(a[2]),"r"(a[3]),"r"(b[0]),"r"(b[1]));
}
__device__ __forceinline__ void cp16(u32 dst, const void* src){
    asm volatile("cp.async.cg.shared.global [%0], [%1], 16;"::"r"(dst),"l"(src));
}
__device__ __forceinline__ u32 pack2(float x, float y){
    __half2 h = __floats2half2_rn(x, y);
    return *(u32*)&h;
}

// ---------------- c_prep1: convA + convB + head-pack ----------------
__global__ __launch_bounds__(256) void c_prep1(
    const float* __restrict__ people, const float* __restrict__ objects,
    const float* __restrict__ context,
    const float* __restrict__ Wvis_w, const float* __restrict__ Who_w,
    const float* __restrict__ Woh_w,
    const float* __restrict__ Wip_w,  const float* __restrict__ Wref_w,
    const float* __restrict__ Watt_w)
{
    __shared__ float t[32][33];
    int bid = blockIdx.x;
    int tid = threadIdx.x;

    if (bid < 8704) {
        int idx = bid*256 + tid;
        const float* src; __half *dh, *dl; int e;
        if (idx < 1048576)      { src = people;  dh = g_peh; dl = g_pel; e = idx; }
        else if (idx < 2097152) { src = objects; dh = g_obh; dl = g_obl; e = idx - 1048576; }
        else                    { src = context; dh = g_cxh; dl = g_cxl; e = idx - 2097152; }
        float v = 0.f;
        if (dh != g_cxh || (e >> 10) < 64) v = src[e];
        __half h = __float2half(v);
        dh[e] = h;
        dl[e] = __float2half(v - __half2float(h));
    } else if (bid < 12288) {
        int lb = bid - 8704;
        const float* W; __half *dh; int N, local;
        if (lb < 512)        { W = Wvis_w;            dh = g_Bv0h; N = 512;  local = lb;       }
        else if (lb < 1024)  { W = Wvis_w + 1024*512; dh = g_Bv1h; N = 512;  local = lb - 512; }
        else if (lb < 1536)  { W = Wvis_w + 2048*512; dh = g_Bv2h; N = 512;  local = lb - 1024;}
        else if (lb < 2560)  { W = Who_w;             dh = g_Whoh; N = 1024; local = lb - 1536;}
        else                 { W = Woh_w;             dh = g_Wohh; N = 1024; local = lb - 2560;}
        int ntN = N >> 5;
        int k0 = (local / ntN) * 32, n0 = (local % ntN) * 32;
        #pragma unroll
        for (int i = 0; i < 4; i++) {
            int e = tid + i*256, r = e >> 5, c = e & 31;
            t[r][c] = W[(k0 + r)*N + n0 + c];
        }
        __syncthreads();
        #pragma unroll
        for (int i = 0; i < 4; i++) {
            int e = tid + i*256, r = e >> 5, c = e & 31;
            dh[(n0 + r)*1024 + k0 + c] = __float2half(t[c][r]);
        }
    } else {
        int idx = (bid - 12288)*256 + tid;
        int c = idx >> 9, k = idx & 511;
        float v = 0.f;
        if (c == 0)                  v = Wip_w[k];
        else if (c <= 29)            v = Wref_w[k*29 + c - 1];
        else if (c >= 32 && c <= 60) v = Watt_w[k*29 + c - 32];
        g_Wcath[idx] = __float2half(v);
    }
}

// ---------------- c_prep2: spatial + Wspat^T ----------------
__global__ __launch_bounds__(256) void c_prep2(
    const float* __restrict__ spatial, const float* __restrict__ Wspat_w)
{
    int bid = blockIdx.x;
    int tid = threadIdx.x;
    if (bid < 2048) {
        int idx = bid*256 + tid;
        float v = spatial[idx];
        __half h = __float2half(v);
        g_sph[idx] = h;
        g_spl[idx] = __float2half(v - __half2float(h));
    } else {
        int idx = (bid - 2048)*256 + tid;
        g_Wsh[idx] = __float2half(Wspat_w[(idx & 31)*512 + (idx >> 5)]);
    }
}

// ---------------- k1: warp-MMA fp16 2-term split GEMM, 128x64 tiles ----------------
#define KP 40
#define TA (128*KP*2)
#define TB (64*KP*2)
#define STAGE_B (2*TA + TB)
#define K1_SMEM (2*STAGE_B)

__global__ __launch_bounds__(128,3) void k1_mma(
    const float* __restrict__ Wvis_b,
    const float* __restrict__ Who_b,
    const float* __restrict__ Woh_b,
    int boff)
{
    extern __shared__ char smem[];
    u32 sb = smem_u32(smem);
    int tid = threadIdx.x, lane = tid & 31, wid = tid >> 5;
    int wm = wid & 1, wn = wid >> 1;
    int bid = blockIdx.x + boff;

    const __half *Ah, *Al, *Bh;
    float* C; const float* bias = 0;
    int relu = 0, Mv = 1024, N, mt0, nt0, local;
    if (bid < 64)       { Ah=g_peh; Al=g_pel; Bh=g_Bv0h; C=g_Pvis; N=512;  local=bid;     mt0=local>>3; nt0=local&7; }
    else if (bid < 128) { Ah=g_obh; Al=g_obl; Bh=g_Bv1h; C=g_Ovis; N=512;  local=bid-64;  mt0=local>>3; nt0=local&7; }
    else if (bid < 136) { Ah=g_cxh; Al=g_cxl; Bh=g_Bv2h; C=g_Cvis; N=512;  local=bid-128; mt0=0; nt0=local; bias=Wvis_b; Mv=64; }
    else if (bid < 264) { Ah=g_peh; Al=g_pel; Bh=g_Whoh; C=g_HO;   N=1024; local=bid-136; mt0=local>>4; nt0=local&15; bias=Who_b; relu=1; }
    else                { Ah=g_obh; Al=g_obl; Bh=g_Wohh; C=g_OH;   N=1024; local=bid-264; mt0=local>>4; nt0=local&15; bias=Woh_b; relu=1; }
    int m0 = mt0 * 128, n0 = nt0 * 64;

    float acc[4][4][4];
    #pragma unroll
    for (int i = 0; i < 4; i++)
        #pragma unroll
        for (int j = 0; j < 4; j++)
            #pragma unroll
            for (int q = 0; q < 4; q++) acc[i][j][q] = 0.f;

    int lg = lane >> 3, lr = lane & 7;
    int a_row_off = lr + ((lg & 1) << 3);
    int a_k_off   = (lg >> 1) << 3;
    int b4_row_off = ((lane >> 4) << 3) + lr;
    int b4_k_off   = ((lane >> 3) & 1) << 3;

    #define LOAD_STAGE(KT, S) do {                                                    \
        u32 _s = (S); int _kt = (KT);                                                 \
        _Pragma("unroll")                                                             \
        for (int i = 0; i < 4; i++) {                                                 \
            int e = tid + i*128, row = e >> 2, sg = (e & 3) * 8;                      \
            cp16(_s      + (row*KP + sg)*2, &Ah[(m0 + row)*1024 + _kt + sg]);         \
            cp16(_s + TA + (row*KP + sg)*2, &Al[(m0 + row)*1024 + _kt + sg]);         \
        }                                                                             \
        _Pragma("unroll")                                                             \
        for (int i = 0; i < 2; i++) {                                                 \
            int e = tid + i*128, row = e >> 2, sg = (e & 3) * 8;                      \
            cp16(_s + 2*TA + (row*KP + sg)*2, &Bh[(n0 + row)*1024 + _kt + sg]);       \
        }                                                                             \
        asm volatile("cp.async.commit_group;");                                       \
    } while(0)

    LOAD_STAGE(0, sb);

    for (int c = 0; c < 32; c++) {
        asm volatile("cp.async.wait_group 0;");
        __syncthreads();
        if (c < 31) LOAD_STAGE((c + 1)*32, sb + ((c + 1) & 1)*STAGE_B);

        u32 st  = sb + (c & 1)*STAGE_B;
        u32 sAh = st, sAl = st + TA, sBh = st + 2*TA;

        #pragma unroll
        for (int ks = 0; ks < 32; ks += 16) {
            u32 bh[4][2];
            #pragma unroll
            for (int j = 0; j < 2; j++) {
                u32 boff2 = ((wn*32 + j*16 + b4_row_off)*KP + ks + b4_k_off) * 2;
                u32 r4[4];
                ldm_x4(r4, sBh + boff2);
                bh[j*2][0] = r4[0]; bh[j*2][1] = r4[1]; bh[j*2+1][0] = r4[2]; bh[j*2+1][1] = r4[3];
            }
            #pragma unroll
            for (int mt = 0; mt < 4; mt++) {
                u32 aoff = ((wm*64 + mt*16 + a_row_off)*KP + ks + a_k_off) * 2;
                u32 ah[4], al[4];
                ldm_x4(ah, sAh + aoff);
                ldm_x4(al, sAl + aoff);
                #pragma unroll
                for (int nt = 0; nt < 4; nt++) {
                    mma_f16(acc[mt][nt], ah, bh[nt]);
                    mma_f16(acc[mt][nt], al, bh[nt]);
                }
            }
        }
    }

    int rq = lane >> 2, cq = (lane & 3) * 2;
    #pragma unroll
    for (int mt = 0; mt < 4; mt++) {
        int gmA = m0 + wm*64 + mt*16 + rq;
        int gmB = gmA + 8;
        #pragma unroll
        for (int nt = 0; nt < 4; nt++) {
            int gn = n0 + wn*32 + nt*8 + cq;
            float b0 = bias ? bias[gn]   : 0.f;
            float b1 = bias ? bias[gn+1] : 0.f;
            float v0 = acc[mt][nt][0] + b0, v1 = acc[mt][nt][1] + b1;
            float v2 = acc[mt][nt][2] + b0, v3 = acc[mt][nt][3] + b1;
            if (relu) { v0=fmaxf(v0,0.f); v1=fmaxf(v1,0.f); v2=fmaxf(v2,0.f); v3=fmaxf(v3,0.f); }
            if (gmA < Mv) *(float2*)&C[gmA*N + gn] = make_float2(v0, v1);
            if (gmB < Mv) *(float2*)&C[gmB*N + gn] = make_float2(v2, v3);
        }
    }
}

// ---------------- k2 (R12 version): MMA phase1 + smem-staged MMA heads ----------------
#define K2P 520
#define OFF_AH  0
#define OFF_AL  1280
#define OFF_WS  2560
#define OFF_FAH 43520
#define OFF_WH  76800
#define K2_SMEM 94208

__global__ __launch_bounds__(256,2) void k2_pairs(
    const float* __restrict__ Wspat_b,
    const float* __restrict__ Wip_b,   const float* __restrict__ Wref_b,
    const float* __restrict__ Watt_b,  float* __restrict__ out)
{
    extern __shared__ char sm2[];
    __half* s_ws  = (__half*)(sm2 + OFF_WS);    // [512][40]
    __half* s_fah = (__half*)(sm2 + OFF_FAH);   // [32][520]
    __half* s_wh  = (__half*)(sm2 + OFF_WH);    // [64][136]

    int tid = threadIdx.x;
    int bp = blockIdx.x;
    int b = bp >> 4;
    int lane = tid & 31, wid = tid >> 5;

    {
        int l = tid >> 4, kq = tid & 15;
        ((u32*)(sm2 + OFF_AH))[l*20 + kq] = ((const u32*)g_sph)[(bp*16 + l)*16 + kq];
        ((u32*)(sm2 + OFF_AL))[l*20 + kq] = ((const u32*)g_spl)[(bp*16 + l)*16 + kq];
    }
    #pragma unroll
    for (int i = 0; i < 8; i++) {
        int e = tid + i*256;
        int n = e >> 2, seg = (e & 3) * 8;
        *(uint4*)&s_ws[n*40 + seg] = *(const uint4*)&g_Wsh[n*32 + seg];
    }
    __syncthreads();

    int lg = lane >> 3, lr = lane & 7;
    int a_row_off = lr + ((lg & 1) << 3);
    int a_koff = (lg >> 1) << 3;
    u32 ah0[4], ah1[4], al0[4], al1[4];
    {
        u32 bah = smem_u32(sm2 + OFF_AH), bal = smem_u32(sm2 + OFF_AL);
        u32 aoff = (a_row_off*40 + a_koff)*2;
        ldm_x4(ah0, bah + aoff);
        ldm_x4(ah1, bah + aoff + 32);
        ldm_x4(al0, bal + aoff);
        ldm_x4(al1, bal + aoff + 32);
    }

    int lq = lane & 3, ln = lane >> 2;
    u32 base_ws = smem_u32(s_ws);
    int ws_koff = (lane >> 3) << 3;
    #pragma unroll
    for (int nt = 0; nt < 8; nt++) {
        u32 bh[4];
        ldm_x4(bh, base_ws + ((wid*64 + nt*8 + lr)*40 + ws_koff)*2);
        float c[4] = {0.f, 0.f, 0.f, 0.f};
        mma_f16(c, ah0, bh);
        mma_f16(c, al0, bh);
        mma_f16(c, ah1, bh + 2);
        mma_f16(c, al1, bh + 2);

        int j0 = wid*64 + nt*8 + lq*2;
        int l0 = ln, l1 = ln + 8;
        float2 bs = *(const float2*)&Wspat_b[j0];
        float2 pv = *(const float2*)&g_Pvis[bp*512 + j0];
        float2 cv = *(const float2*)&g_Cvis[b*512 + j0];
        float2 o0 = *(const float2*)&g_Ovis[(b*16 + l0)*512 + j0];
        float2 o1 = *(const float2*)&g_Ovis[(b*16 + l1)*512 + j0];
        float a0 = fmaxf(c[0] + bs.x, 0.f), a1 = fmaxf(c[1] + bs.y, 0.f);
        float a2 = fmaxf(c[2] + bs.x, 0.f), a3 = fmaxf(c[3] + bs.y, 0.f);
        float f0 = fmaxf(pv.x + o0.x + cv.x, 0.f) * a0;
        float f1 = fmaxf(pv.y + o0.y + cv.y, 0.f) * a1;
        float f2 = fmaxf(pv.x + o1.x + cv.x, 0.f) * a2;
        float f3 = fmaxf(pv.y + o1.y + cv.y, 0.f) * a3;
        *(u32*)&s_fah[l0*K2P + j0]        = pack2(f0, f1);
        *(u32*)&s_fah[l1*K2P + j0]        = pack2(f2, f3);
        *(u32*)&s_fah[(16 + l0)*K2P + j0] = pack2(a0, a1);
        *(u32*)&s_fah[(16 + l1)*K2P + j0] = pack2(a2, a3);
    }

    // ---- phase 2: [32 rows] @ heads via fp16 MMA, s_wh staged in 4 chunks ----
    int mt = wid >> 2;
    int ntile = (wid & 3) + mt*4;
    u32 base_fah = smem_u32(s_fah);
    u32 base_wh  = smem_u32(s_wh);
    int a_row = mt*16 + lr + ((lg & 1) << 3);
    int b_row = ntile*8 + lr;
    int b4_koff = (lane >> 3) << 3;

    float acc2[4] = {0.f, 0.f, 0.f, 0.f};

    for (int kc = 0; kc < 4; kc++) {
        __syncthreads();
        #pragma unroll
        for (int i = 0; i < 4; i++) {
            int e = tid + i*256;
            int c = e >> 4, k8 = (e & 15) << 3;
            *(uint4*)&s_wh[c*136 + k8] = *(const uint4*)&g_Wcath[c*512 + kc*128 + k8];
        }
        __syncthreads();
        #pragma unroll
        for (int ks = 0; ks < 128; ks += 32) {
            u32 bh4[4];
            ldm_x4(bh4, base_wh + (b_row*136 + ks + b4_koff)*2);
            u32 xh0[4], xh1[4];
            ldm_x4(xh0, base_fah + (a_row*K2P + kc*128 + ks + a_koff)*2);
            ldm_x4(xh1, base_fah + (a_row*K2P + kc*128 + ks + 16 + a_koff)*2);
            mma_f16(acc2, xh0, bh4);
            mma_f16(acc2, xh1, bh4 + 2);
        }
    }

    int r0 = mt*16 + (lane >> 2);
    int c0 = ntile*8 + (lane & 3)*2;
    #pragma unroll
    for (int q = 0; q < 4; q++) {
        int r = r0 + ((q >> 1) << 3);
        int c = c0 + (q & 1);
        float v = acc2[q];
        if (r < 16) {
            int cidx = bp*16 + r;
            if (c == 0) {
                v += Wip_b[0];
                out[cidx] = v;
                g_adj[cidx] = 1.f / (1.f + expf(-v));
            } else if (c <= 29) {
                out[16384 + cidx*29 + (c - 1)] = v + Wref_b[c - 1];
            }
        } else {
            int cidx = bp*16 + (r - 16);
            int cc = c - 32;
            if (cc >= 0 && cc <= 28) {
                out[491520 + cidx*29 + cc] = v + Watt_b[cc];
            }
        }
    }
}

// ---------------- k3a: message passing ----------------
__global__ __launch_bounds__(256) void k3a_msg(const float* __restrict__ people,
                                               const float* __restrict__ objects)
{
    __shared__ float adj[240];
    int bid = blockIdx.x;
    int b = bid >> 3, ch = (bid >> 1) & 3, role = bid & 1;
    int tid = threadIdx.x;
    if (tid < 240) adj[tid] = g_adj[(b*16 + tid/15)*16 + (tid % 15) + 1];
    __syncthreads();

    int d = ch*256 + tid;
    if (role == 0) {
        float oh[15];
        #pragma unroll
        for (int o = 0; o < 15; o++) oh[o] = g_OH[(b*16 + o + 1)*1024 + d];
        #pragma unroll
        for (int p = 0; p < 16; p++) {
            float acc = people[(b*16 + p)*1024 + d];
            #pragma unroll
            for (int o = 0; o < 15; o++) acc += adj[p*15 + o] * oh[o];
            g_PR[(b*16 + p)*1024 + d] = acc;
        }
    } else {
        float ho[16];
        #pragma unroll
        for (int p = 0; p < 16; p++) ho[p] = g_HO[(b*16 + p)*1024 + d];
        g_OBF[(b*16)*1024 + d] = objects[(b*16)*1024 + d];
        #pragma unroll
        for (int o = 0; o < 15; o++) {
            float acc = objects[(b*16 + o + 1)*1024 + d];
            #pragma unroll
            for (int p = 0; p < 16; p++) acc += adj[p*15 + o] * ho[p];
            g_OBF[(b*16 + o + 1)*1024 + d] = acc;
        }
    }
}

// ---------------- k3b: skinny GEMM warp-per-row ----------------
__global__ __launch_bounds__(256) void k3b_gemm(const float* __restrict__ Wg_w,
                                                const float* __restrict__ Wg_b)
{
    __shared__ float Ws[256*33];
    int half = blockIdx.x >> 7;
    int row = (blockIdx.x & 127)*8 + (threadIdx.x >> 5);
    int lane = threadIdx.x & 31;
    const float* src = half ? g_OBF : g_PR;
    const float* W = Wg_w + half*1024*29;
    float* dst = half ? g_Go : g_Gp;

    float acc[29];
    #pragma unroll
    for (int a = 0; a < 29; a++) acc[a] = 0.f;

    for (int kt = 0; kt < 4; kt++) {
        __syncthreads();
        #pragma unroll
        for (int i = 0; i < 29; i++) {
            int idx = threadIdx.x + i*256;
            int k = idx / 29, a = idx - k*29;
            Ws[k*33 + a] = W[kt*7424 + idx];
        }
        __syncthreads();
        #pragma unroll
        for (int t = 0; t < 8; t++) {
            int k = t*32 + lane;
            float rv = src[row*1024 + kt*256 + k];
            #pragma unroll
            for (int a = 0; a < 29; a++) acc[a] += rv * Ws[k*33 + a];
        }
    }
    #pragma unroll
    for (int off = 16; off; off >>= 1)
        #pragma unroll
        for (int a = 0; a < 29; a++)
            acc[a] += __shfl_down_sync(0xffffffffu, acc[a], off);
    if (lane == 0) {
        #pragma unroll
        for (int a = 0; a < 29; a++)
            dst[row*29 + a] = acc[a] + (half ? Wg_b[a] : 0.f);
    }
}

// ---------------- k3c: broadcast add ----------------
__global__ __launch_bounds__(256) void k3c_add(float* __restrict__ out_pg)
{
    int idx = blockIdx.x*256 + threadIdx.x;
    int c = idx / 29;
    int a = idx - c*29;
    int prow = c >> 4;
    int lrow = (c >> 8)*16 + (c & 15);
    out_pg[idx] = g_Gp[prow*29 + a] + g_Go[lrow*29 + a];
}

// ---------------- launch: R12 fork structure + prep2 overlap ----------------
extern "C" void kernel_launch(void* const* d_in, const int* in_sizes, int n_in,
                              void* d_out, int out_size) {
    const float* people  = (const float*)d_in[0];
    const float* objects = (const float*)d_in[1];
    const float* context = (const float*)d_in[2];
    const float* spatial = (const float*)d_in[3];
    const float* Wvis_w  = (const float*)d_in[4];
    const float* Wvis_b  = (const float*)d_in[5];
    const float* Wspat_w = (const float*)d_in[6];
    const float* Wspat_b = (const float*)d_in[7];
    const float* Wip_w   = (const float*)d_in[8];
    const float* Wip_b   = (const float*)d_in[9];
    const float* Wref_w  = (const float*)d_in[10];
    const float* Wref_b  = (const float*)d_in[11];
    const float* Watt_w  = (const float*)d_in[12];
    const float* Watt_b  = (const float*)d_in[13];
    const float* Woh_w   = (const float*)d_in[14];
    const float* Woh_b   = (const float*)d_in[15];
    const float* Who_w   = (const float*)d_in[16];
    const float* Who_b   = (const float*)d_in[17];
    const float* Wg_w    = (const float*)d_in[18];
    const float* Wg_b    = (const float*)d_in[19];
    float* out = (float*)d_out;

    cudaFuncSetAttribute(k1_mma,  cudaFuncAttributeMaxDynamicSharedMemorySize, K1_SMEM);
    cudaFuncSetAttribute(k2_pairs, cudaFuncAttributeMaxDynamicSharedMemorySize, K2_SMEM);

    cudaStream_t s1;
    cudaStreamCreateWithFlags(&s1, cudaStreamNonBlocking);
    cudaEvent_t evF, evA, ev1, ev2;
    cudaEventCreateWithFlags(&evF, cudaEventDisableTiming);
    cudaEventCreateWithFlags(&evA, cudaEventDisableTiming);
    cudaEventCreateWithFlags(&ev1, cudaEventDisableTiming);
    cudaEventCreateWithFlags(&ev2, cudaEventDisableTiming);

    // fork point (capture-legal: side stream first waits on origin event)
    cudaEventRecord(evF, 0);
    cudaStreamWaitEvent(s1, evF, 0);

    // side stream: k2-only conversions
    c_prep2<<<2112, 256, 0, s1>>>(spatial, Wspat_w);
    cudaEventRecord(ev2, s1);

    // origin stream: main conversions
    c_prep1<<<12416, 256>>>(people, objects, context,
                            Wvis_w, Who_w, Woh_w, Wip_w, Wref_w, Watt_w);
    cudaEventRecord(evA, 0);

    // side stream: k1b (HO/OH) after c_prep1
    cudaStreamWaitEvent(s1, evA, 0);
    k1_mma<<<256, 128, K1_SMEM, s1>>>(Wvis_b, Who_b, Woh_b, 136);
    cudaEventRecord(ev1, s1);

    // origin stream: k1a then k2
    k1_mma<<<136, 128, K1_SMEM>>>(Wvis_b, Who_b, Woh_b, 0);
    cudaStreamWaitEvent(0, ev2, 0);
    k2_pairs<<<1024, 256, K2_SMEM>>>(Wspat_b, Wip_b, Wref_b, Watt_b, out);

    // join: k3 chain needs k1b + k2
    cudaStreamWaitEvent(0, ev1, 0);
    k3a_msg<<<512, 256>>>(people, objects);
    k3b_gemm<<<256, 256>>>(Wg_w, Wg_b);
    k3c_add<<<1856, 256>>>(out + 966656);

    cudaEventDestroy(evF);
    cudaEventDestroy(evA);
    cudaEventDestroy(ev1);
    cudaEventDestroy(ev2);
    cudaStreamDestroy(s1);
}